// round 2
// baseline (speedup 1.0000x reference)
#include <cuda_runtime.h>
#include <cstdint>
#include <cstddef>

// ---------------------------------------------------------------------------
// RyeElman fused kernel.
//
// Math restructuring:
//   proj[h] = sum_s (xn_s . Wl[:,h]) (xn_s . Wr[:,h])
//           = sum_{c<=c'} Mn[c,c'] * G[(c,c'),h]
//   where Mn[c,c'] = (sum_s e[s,c]e[s,c']) / (norm[c]*norm[c'])   (153 packed)
//         G[(c,c'),h] = Wl[c,h]Wr[c',h] + (c!=c') Wl[c',h]Wr[c,h]
//
// Whole invariant path + damping gate is ONE GEMM:
//   A [B x 352] = [inv_input(64) | inv_hidden(128) | Mn(153) | zeros(7)]
//   Wbig [352 x 144] = [[W_ii | W_damp]; [G | 0]; [0]]
//   out[:, :128] -> tanh(+b_ii) = new_invariant ; out[:,128:144] = gate
// Computed in tf32 via mma.sync (fp32 accumulate), fully fused per 128-row tile.
// ---------------------------------------------------------------------------

#define BDIM 512
#define ROWS_PER_BLK 128
#define KD   192            // I + H
#define NPAIR 153           // 17*18/2
#define KA   352            // 192 + 153 padded to mult of 32
#define ASTR 353            // A panel smem stride (pad for banks)
#define NW   144            // 128 + 16 output cols
#define WSTR 145            // W slice smem stride
#define ESTR 52             // eq_comb smem stride (51 + pad)
#define NSLICE 11           // 352 / 32
#define PF 9                // (32*144)/512 prefetch elems per thread

__device__ float d_Wbig[KA * NW];   // static device scratch (no allocs allowed)

__device__ __forceinline__ unsigned tf32u(float x) {
    unsigned u;
    asm("cvt.rna.tf32.f32 %0, %1;" : "=r"(u) : "f"(x));
    return u;
}
__device__ __forceinline__ float tf32f(float x) { return __uint_as_float(tf32u(x)); }

__device__ __forceinline__ void mma_tf32(float* c, unsigned a0, unsigned a1,
                                         unsigned a2, unsigned a3,
                                         unsigned b0, unsigned b1) {
    asm volatile(
        "mma.sync.aligned.m16n8k8.row.col.f32.tf32.tf32.f32 "
        "{%0,%1,%2,%3}, {%4,%5,%6,%7}, {%8,%9}, {%0,%1,%2,%3};"
        : "+f"(c[0]), "+f"(c[1]), "+f"(c[2]), "+f"(c[3])
        : "r"(a0), "r"(a1), "r"(a2), "r"(a3), "r"(b0), "r"(b1));
}

// ---------------------------------------------------------------------------
// K0: build Wbig (tf32-rounded) from W_ii, W_damp, W_left, W_right.
// ---------------------------------------------------------------------------
__global__ void prep_w_kernel(const float* __restrict__ Wii,
                              const float* __restrict__ Wdamp,
                              const float* __restrict__ Wl,
                              const float* __restrict__ Wr) {
    int idx = blockIdx.x * blockDim.x + threadIdx.x;
    if (idx >= KA * NW) return;
    int k = idx / NW, j = idx - k * NW;
    float v = 0.f;
    if (k < KD) {
        v = (j < 128) ? Wii[k * 128 + j] : Wdamp[k * 16 + (j - 128)];
    } else if (k < KD + NPAIR && j < 128) {
        int p = k - KD, c = 0, rem = p;
        while (rem >= 17 - c) { rem -= 17 - c; c++; }
        int c2 = c + rem;
        float g = Wl[c * 128 + j] * Wr[c2 * 128 + j];
        if (c2 != c) g += Wl[c2 * 128 + j] * Wr[c * 128 + j];
        v = g;
    }
    d_Wbig[idx] = tf32f(v);
}

// ---------------------------------------------------------------------------
// K1: fused main kernel. One block = 128 batch rows, 512 threads (16 warps).
// Warp grid 8 (rows) x 2 (cols): each warp = 1 m16-tile x 9 n8-tiles.
// ---------------------------------------------------------------------------
__global__ __launch_bounds__(BDIM, 1)
void rye_main(const float* __restrict__ invi, const float* __restrict__ eqi,
              const float* __restrict__ invh, const float* __restrict__ eqh,
              const float* __restrict__ bii,  const float* __restrict__ Wee,
              float* __restrict__ out, int Btot) {
    extern __shared__ float sm[];
    float* As    = sm;                              // 128*353 floats
    float* Es    = As + ROWS_PER_BLK * ASTR;        // 128*52  (eq_comb rows)
    float* Ws    = Es + ROWS_PER_BLK * ESTR;        // 32*145  (W k-slice)
    float* Wee_s = Ws + 32 * WSTR;                  // 288 (17x16 W_ee)
    float* Gs    = Ws;                              // reused post-GEMM: 128x16 gates

    int tid  = threadIdx.x;
    int row0 = blockIdx.x * ROWS_PER_BLK;

    // ---- Stage A-panel invariant region (tf32-rounded) ----
    for (int t = tid; t < ROWS_PER_BLK * 64; t += BDIM) {
        int r = t >> 6, k = t & 63;
        As[r * ASTR + k] = tf32f(invi[(size_t)(row0 + r) * 64 + k]);
    }
    for (int t = tid; t < ROWS_PER_BLK * 128; t += BDIM) {
        int r = t >> 7, k = t & 127;
        As[r * ASTR + 64 + k] = tf32f(invh[(size_t)(row0 + r) * 128 + k]);
    }
    for (int t = tid; t < ROWS_PER_BLK * 7; t += BDIM) {   // K padding cols 345..351
        int r = t / 7, k = t - r * 7;
        As[r * ASTR + 345 + k] = 0.f;
    }
    // ---- Stage eq_comb rows: [eqi(s) | eqh(s, 0..15)] per s, 51 floats/row ----
    for (int t = tid; t < ROWS_PER_BLK * 48; t += BDIM) {
        int r = t / 48, q = t - r * 48;
        int s = q >> 4, c = q & 15;
        Es[r * ESTR + s * 17 + 1 + c] = eqh[(size_t)(row0 + r) * 48 + q];
    }
    for (int t = tid; t < ROWS_PER_BLK * 3; t += BDIM) {
        int r = t / 3, s = t - r * 3;
        Es[r * ESTR + s * 17] = eqi[(size_t)(row0 + r) * 3 + s];
    }
    if (tid < 17 * 16) Wee_s[tid] = Wee[tid];
    // stage W slice 0 while waiting
    for (int t = tid; t < 32 * NW; t += BDIM) {
        int kk = t / NW, j = t - kk * NW;
        Ws[kk * WSTR + j] = d_Wbig[kk * NW + j];
    }
    __syncthreads();

    // ---- Build Mn into A-panel cols [192, 345): 4 threads per row ----
    {
        int r = tid >> 2, sub = tid & 3;
        const float* E = Es + r * ESTR;
        float invn[17];
#pragma unroll
        for (int c = 0; c < 17; c++) {
            float e0 = E[c], e1 = E[17 + c], e2 = E[34 + c];
            float n = fmaf(e0, e0, fmaf(e1, e1, fmaf(e2, e2, 1e-6f)));
            invn[c] = __frcp_rn(n);
        }
        int p = 0;
#pragma unroll
        for (int c = 0; c < 17; c++) {
#pragma unroll
            for (int c2 = c; c2 < 17; c2++, p++) {
                if ((p & 3) == sub) {
                    float g = E[c] * E[c2] + E[17 + c] * E[17 + c2] + E[34 + c] * E[34 + c2];
                    As[r * ASTR + KD + p] = tf32f(g * invn[c] * invn[c2]);
                }
            }
        }
    }
    __syncthreads();

    // ---- GEMM: A[128x352] @ Wbig[352x144] in tf32 mma.sync ----
    int wid = tid >> 5, lane = tid & 31;
    int rowW = wid >> 1, colW = wid & 1;
    int m0 = rowW * 16;
    int n0w = colW * 72;
    int g = lane >> 2, t4 = lane & 3;

    float acc[9][4];
#pragma unroll
    for (int i = 0; i < 9; i++) { acc[i][0] = acc[i][1] = acc[i][2] = acc[i][3] = 0.f; }

    for (int ksl = 0; ksl < NSLICE; ksl++) {
        // prefetch next slice into registers (overlaps with mma compute)
        float pf[PF];
        if (ksl + 1 < NSLICE) {
            const float* src = d_Wbig + (ksl + 1) * 32 * NW;
#pragma unroll
            for (int i = 0; i < PF; i++) pf[i] = src[tid + i * BDIM];
        }
#pragma unroll
        for (int ks = 0; ks < 4; ks++) {
            int kb = ksl * 32 + ks * 8;                 // GLOBAL k offset into A
            const float* Arow = As + (m0 + g) * ASTR + kb + t4;
            unsigned a0 = __float_as_uint(Arow[0]);
            unsigned a1 = __float_as_uint(Arow[8 * ASTR]);
            unsigned a2 = __float_as_uint(Arow[4]);
            unsigned a3 = __float_as_uint(Arow[8 * ASTR + 4]);
            const float* Bbase = Ws + (ks * 8 + t4) * WSTR + n0w + g;   // slice-local k
#pragma unroll
            for (int nt = 0; nt < 9; nt++) {
                unsigned b0 = __float_as_uint(Bbase[nt * 8]);
                unsigned b1 = __float_as_uint(Bbase[4 * WSTR + nt * 8]);
                mma_tf32(acc[nt], a0, a1, a2, a3, b0, b1);
            }
        }
        __syncthreads();
        if (ksl + 1 < NSLICE) {
#pragma unroll
            for (int i = 0; i < PF; i++) {
                int e = tid + i * BDIM;
                int kk = e / NW, j = e - kk * NW;
                Ws[kk * WSTR + j] = pf[i];
            }
            __syncthreads();
        }
    }

    // ---- Epilogue: tanh(+bias) -> new_invariant; gate cols -> smem ----
    int lr = m0 + g;
#pragma unroll
    for (int nt = 0; nt < 9; nt++) {
        int j = n0w + nt * 8 + 2 * t4;
        if (j < 128) {
            float b0 = bii[j], b1 = bii[j + 1];
            float2 v0 = make_float2(tanhf(acc[nt][0] + b0), tanhf(acc[nt][1] + b1));
            float2 v1 = make_float2(tanhf(acc[nt][2] + b0), tanhf(acc[nt][3] + b1));
            *reinterpret_cast<float2*>(&out[(size_t)(row0 + lr) * 128 + j])     = v0;
            *reinterpret_cast<float2*>(&out[(size_t)(row0 + lr + 8) * 128 + j]) = v1;
        } else {
            int jc = j - 128;
            Gs[lr * 16 + jc]           = acc[nt][0];
            Gs[lr * 16 + jc + 1]       = acc[nt][1];
            Gs[(lr + 8) * 16 + jc]     = acc[nt][2];
            Gs[(lr + 8) * 16 + jc + 1] = acc[nt][3];
        }
    }
    __syncthreads();

    // ---- new_equivariant = eq_comb @ W_ee + eqh * gate ----
    size_t eq_base = (size_t)Btot * 128;
    for (int t = tid; t < ROWS_PER_BLK * 48; t += BDIM) {
        int r = t / 48, q = t - r * 48;
        int s = q >> 4, c = q & 15;
        const float* E = Es + r * ESTR + s * 17;
        float sum = 0.f;
#pragma unroll
        for (int cc = 0; cc < 17; cc++) sum = fmaf(E[cc], Wee_s[cc * 16 + c], sum);
        sum = fmaf(E[1 + c], Gs[r * 16 + c], sum);
        out[eq_base + (size_t)(row0 + r) * 48 + q] = sum;
    }
}

// ---------------------------------------------------------------------------
extern "C" void kernel_launch(void* const* d_in, const int* in_sizes, int n_in,
                              void* d_out, int out_size) {
    const float* invi  = (const float*)d_in[0];  // [B,64]
    const float* eqi   = (const float*)d_in[1];  // [B,3]
    const float* invh  = (const float*)d_in[2];  // [B,128]
    const float* eqhid = (const float*)d_in[3];  // [B,3,16]
    const float* Wl    = (const float*)d_in[4];  // [17,128]
    const float* Wr    = (const float*)d_in[5];  // [17,128]
    const float* Wii   = (const float*)d_in[6];  // [192,128]
    const float* bii   = (const float*)d_in[7];  // [128]
    const float* Wee   = (const float*)d_in[8];  // [17,16]
    const float* Wdamp = (const float*)d_in[9];  // [192,16]
    float* out = (float*)d_out;

    int Btot = in_sizes[0] / 64;

    prep_w_kernel<<<(KA * NW + 255) / 256, 256>>>(Wii, Wdamp, Wl, Wr);

    int smem_bytes = (ROWS_PER_BLK * ASTR + ROWS_PER_BLK * ESTR + 32 * WSTR + 288) * 4;
    cudaFuncSetAttribute(rye_main, cudaFuncAttributeMaxDynamicSharedMemorySize, smem_bytes);
    rye_main<<<Btot / ROWS_PER_BLK, BDIM, smem_bytes>>>(invi, eqi, invh, eqhid,
                                                        bii, Wee, out, Btot);
}

// round 3
// speedup vs baseline: 1.6575x; 1.6575x over previous
#include <cuda_runtime.h>
#include <cstdint>
#include <cstddef>

// ---------------------------------------------------------------------------
// RyeElman fused kernel, round 3.
//
//   proj[h] = sum_{c<=c'} Mn[c,c'] * G[(c,c'),h]   (Gram factorization)
//   One GEMM: A[B x 352] @ Wbig[352 x 144]
//     A = [inv_input(64) | inv_hidden(128) | Mn(153) | 0(7)]
//     Wbig = [[W_ii | W_damp]; [G | 0]; [0]]
//   tf32 mma.sync m16n8k8, fp32 accum.
//
// R3 changes: B operand streamed straight from a fragment-major global table
// (no smem staging, no in-loop barriers), A panel in a permuted smem layout
// enabling LDS.64 fragment loads, Es panel dropped (Gram from registers).
// ---------------------------------------------------------------------------

#define BDIM 512
#define ROWS_PER_BLK 128
#define KD   192
#define NPAIR 153
#define KA   352
#define ASTR 360            // ≡ 8 (mod 32): conflict-free LDS.64 A-fragment loads
#define NKS  44             // 352 / 8 k-steps
#define FRAG_ELEMS (NKS * 2 * 32 * 20)   // 56320

__device__ float d_Wfrag[FRAG_ELEMS];    // fragment-major weights (static scratch)

__device__ __forceinline__ unsigned tf32u(float x) {
    unsigned u;
    asm("cvt.rna.tf32.f32 %0, %1;" : "=r"(u) : "f"(x));
    return u;
}
__device__ __forceinline__ float tf32f(float x) { return __uint_as_float(tf32u(x)); }

// permuted A column: within each k-octet store order [0,4,1,5,2,6,3,7]
// so (k, k+4) are adjacent -> one LDS.64 yields (a0, a2).
__device__ __forceinline__ int acol(int k) {
    return (k & ~7) + ((k & 3) << 1) + ((k >> 2) & 1);
}

__device__ __forceinline__ void mma_tf32(float* c, unsigned a0, unsigned a1,
                                         unsigned a2, unsigned a3,
                                         unsigned b0, unsigned b1) {
    asm volatile(
        "mma.sync.aligned.m16n8k8.row.col.f32.tf32.tf32.f32 "
        "{%0,%1,%2,%3}, {%4,%5,%6,%7}, {%8,%9}, {%0,%1,%2,%3};"
        : "+f"(c[0]), "+f"(c[1]), "+f"(c[2]), "+f"(c[3])
        : "r"(a0), "r"(a1), "r"(a2), "r"(a3), "r"(b0), "r"(b1));
}

// ---------------------------------------------------------------------------
// K0: build fragment-major weight table.
// Layout: [t(44)][colW(2)][lane(32)][i(20)]
//   i in [0,9):  b0 for nt=i   -> Wbig[t*8 + t4,     colW*72 + nt*8 + g]
//   i in [9,18): b1 for nt=i-9 -> Wbig[t*8 + t4 + 4, colW*72 + nt*8 + g]
//   i in [18,20): pad = 0
// ---------------------------------------------------------------------------
__global__ void prep_w_kernel(const float* __restrict__ Wii,
                              const float* __restrict__ Wdamp,
                              const float* __restrict__ Wl,
                              const float* __restrict__ Wr) {
    int idx = blockIdx.x * blockDim.x + threadIdx.x;
    if (idx >= FRAG_ELEMS) return;
    int i    = idx % 20;
    int lane = (idx / 20) % 32;
    int colW = (idx / 640) % 2;
    int t    = idx / 1280;
    float v = 0.f;
    if (i < 18) {
        int nt = (i < 9) ? i : i - 9;
        int g = lane >> 2, t4 = lane & 3;
        int k = t * 8 + t4 + ((i < 9) ? 0 : 4);
        int n = colW * 72 + nt * 8 + g;
        if (k < KD) {
            v = (n < 128) ? Wii[k * 128 + n] : Wdamp[k * 16 + (n - 128)];
        } else if (k < KD + NPAIR && n < 128) {
            int p = k - KD, c = 0, rem = p;
            while (rem >= 17 - c) { rem -= 17 - c; c++; }
            int c2 = c + rem;
            float g2 = Wl[c * 128 + n] * Wr[c2 * 128 + n];
            if (c2 != c) g2 += Wl[c2 * 128 + n] * Wr[c * 128 + n];
            v = g2;
        }
    }
    d_Wfrag[idx] = tf32f(v);
}

// ---------------------------------------------------------------------------
// K1: fused main kernel. 512 threads, 128 rows/block, 16 warps = 8(M) x 2(N).
// ---------------------------------------------------------------------------
__global__ __launch_bounds__(BDIM, 1)
void rye_main(const float* __restrict__ invi, const float* __restrict__ eqi,
              const float* __restrict__ invh, const float* __restrict__ eqh,
              const float* __restrict__ bii,  const float* __restrict__ Wee,
              float* __restrict__ out, int Btot) {
    extern __shared__ float sm[];
    float* As    = sm;                              // 128*360
    float* Gs    = As + ROWS_PER_BLK * ASTR;        // 128*16 gates
    float* Wee_s = Gs + ROWS_PER_BLK * 16;          // 272 (+pad)

    int tid  = threadIdx.x;
    int row0 = blockIdx.x * ROWS_PER_BLK;

    // ---- Stage A-panel invariant region (tf32, permuted cols) ----
    for (int t = tid; t < ROWS_PER_BLK * 16; t += BDIM) {   // invi: 16 float4/row
        int r = t >> 4, q = t & 15;
        float4 v = reinterpret_cast<const float4*>(invi + (size_t)(row0 + r) * 64)[q];
        int k0 = q * 4;
        float* Ar = As + r * ASTR;
        Ar[acol(k0)]     = tf32f(v.x);
        Ar[acol(k0 + 1)] = tf32f(v.y);
        Ar[acol(k0 + 2)] = tf32f(v.z);
        Ar[acol(k0 + 3)] = tf32f(v.w);
    }
    for (int t = tid; t < ROWS_PER_BLK * 32; t += BDIM) {   // invh: 32 float4/row
        int r = t >> 5, q = t & 31;
        float4 v = reinterpret_cast<const float4*>(invh + (size_t)(row0 + r) * 128)[q];
        int k0 = 64 + q * 4;
        float* Ar = As + r * ASTR;
        Ar[acol(k0)]     = tf32f(v.x);
        Ar[acol(k0 + 1)] = tf32f(v.y);
        Ar[acol(k0 + 2)] = tf32f(v.z);
        Ar[acol(k0 + 3)] = tf32f(v.w);
    }
    for (int t = tid; t < ROWS_PER_BLK * 7; t += BDIM) {    // K pad 345..351
        int r = t / 7, k = 345 + (t - r * 7);
        As[r * ASTR + acol(k)] = 0.f;
    }
    if (tid < 17 * 16) Wee_s[tid] = Wee[tid];

    // ---- Gram -> A cols [192,345): 4 threads per row, data from global ----
    {
        int r = tid >> 2, sub = tid & 3;
        size_t row = (size_t)(row0 + r);
        float E[51];
        const float4* eh = reinterpret_cast<const float4*>(eqh + row * 48);
#pragma unroll
        for (int s = 0; s < 3; s++) {
            E[s * 17] = __ldg(eqi + row * 3 + s);
#pragma unroll
            for (int q = 0; q < 4; q++) {
                float4 v = __ldg(eh + s * 4 + q);
                E[s * 17 + 1 + q * 4]     = v.x;
                E[s * 17 + 2 + q * 4]     = v.y;
                E[s * 17 + 3 + q * 4]     = v.z;
                E[s * 17 + 4 + q * 4]     = v.w;
            }
        }
        float invn[17];
#pragma unroll
        for (int c = 0; c < 17; c++) {
            float n = fmaf(E[c], E[c], fmaf(E[17 + c], E[17 + c],
                         fmaf(E[34 + c], E[34 + c], 1e-6f)));
            invn[c] = __frcp_rn(n);
        }
        float* Ar = As + r * ASTR;
        int p = 0;
#pragma unroll
        for (int c = 0; c < 17; c++) {
#pragma unroll
            for (int c2 = c; c2 < 17; c2++, p++) {
                if ((p & 3) == sub) {
                    float g = E[c] * E[c2] + E[17 + c] * E[17 + c2] + E[34 + c] * E[34 + c2];
                    Ar[acol(KD + p)] = tf32f(g * invn[c] * invn[c2]);
                }
            }
        }
    }
    __syncthreads();

    // ---- GEMM: barrier-free, B streamed from d_Wfrag (L1/L2 resident) ----
    int wid = tid >> 5, lane = tid & 31;
    int m0  = (wid >> 1) * 16;
    int colW = wid & 1;
    int n0w = colW * 72;
    int g = lane >> 2, t4 = lane & 3;

    const float* wf = d_Wfrag + (colW * 32 + lane) * 20;
    const float* ArowA = As + (m0 + g) * ASTR + 2 * t4;
    const float* ArowB = ArowA + 8 * ASTR;

    float acc[9][4];
#pragma unroll
    for (int i = 0; i < 9; i++) acc[i][0] = acc[i][1] = acc[i][2] = acc[i][3] = 0.f;

    float4 nb0, nb1, nb2, nb3; float2 nb4;
    {
        const float4* p = reinterpret_cast<const float4*>(wf);
        nb0 = p[0]; nb1 = p[1]; nb2 = p[2]; nb3 = p[3];
        nb4 = *reinterpret_cast<const float2*>(wf + 16);
    }
#pragma unroll
    for (int t = 0; t < NKS; t++) {
        float bf[18] = { nb0.x, nb0.y, nb0.z, nb0.w, nb1.x, nb1.y, nb1.z, nb1.w,
                         nb2.x, nb2.y, nb2.z, nb2.w, nb3.x, nb3.y, nb3.z, nb3.w,
                         nb4.x, nb4.y };
        if (t + 1 < NKS) {
            const float4* p = reinterpret_cast<const float4*>(wf + (t + 1) * 1280);
            nb0 = p[0]; nb1 = p[1]; nb2 = p[2]; nb3 = p[3];
            nb4 = *reinterpret_cast<const float2*>(wf + (t + 1) * 1280 + 16);
        }
        float2 a01 = *reinterpret_cast<const float2*>(ArowA + t * 8);  // (a0, a2)
        float2 a23 = *reinterpret_cast<const float2*>(ArowB + t * 8);  // (a1, a3)
        unsigned a0 = __float_as_uint(a01.x), a2 = __float_as_uint(a01.y);
        unsigned a1 = __float_as_uint(a23.x), a3 = __float_as_uint(a23.y);
#pragma unroll
        for (int nt = 0; nt < 9; nt++)
            mma_tf32(acc[nt], a0, a1, a2, a3,
                     __float_as_uint(bf[nt]), __float_as_uint(bf[9 + nt]));
    }

    // ---- Epilogue: invariant tanh; gate cols -> Gs ----
    int lr = m0 + g;
#pragma unroll
    for (int nt = 0; nt < 9; nt++) {
        int j = n0w + nt * 8 + 2 * t4;
        if (j < 128) {
            float b0 = __ldg(bii + j), b1 = __ldg(bii + j + 1);
            float2 v0 = make_float2(tanhf(acc[nt][0] + b0), tanhf(acc[nt][1] + b1));
            float2 v1 = make_float2(tanhf(acc[nt][2] + b0), tanhf(acc[nt][3] + b1));
            *reinterpret_cast<float2*>(&out[(size_t)(row0 + lr) * 128 + j])     = v0;
            *reinterpret_cast<float2*>(&out[(size_t)(row0 + lr + 8) * 128 + j]) = v1;
        } else {
            int jc = j - 128;
            Gs[lr * 16 + jc]           = acc[nt][0];
            Gs[lr * 16 + jc + 1]       = acc[nt][1];
            Gs[(lr + 8) * 16 + jc]     = acc[nt][2];
            Gs[(lr + 8) * 16 + jc + 1] = acc[nt][3];
        }
    }
    __syncthreads();

    // ---- new_equivariant: one thread per (row, s) -> 16 channels ----
    if (tid < ROWS_PER_BLK * 3) {
        int r = tid / 3, s = tid - r * 3;
        size_t row = (size_t)(row0 + r);
        float E[17];
        E[0] = __ldg(eqi + row * 3 + s);
        const float4* eh = reinterpret_cast<const float4*>(eqh + row * 48 + s * 16);
#pragma unroll
        for (int q = 0; q < 4; q++) {
            float4 v = __ldg(eh + q);
            E[1 + q * 4] = v.x; E[2 + q * 4] = v.y; E[3 + q * 4] = v.z; E[4 + q * 4] = v.w;
        }
        float4 res[4];
        float* rf = reinterpret_cast<float*>(res);
#pragma unroll
        for (int c = 0; c < 16; c++) {
            float sum = 0.f;
#pragma unroll
            for (int cc = 0; cc < 17; cc++) sum = fmaf(E[cc], Wee_s[cc * 16 + c], sum);
            rf[c] = fmaf(E[1 + c], Gs[r * 16 + c], sum);
        }
        float4* dst = reinterpret_cast<float4*>(out + (size_t)Btot * 128 + row * 48 + s * 16);
        dst[0] = res[0]; dst[1] = res[1]; dst[2] = res[2]; dst[3] = res[3];
    }
}

// ---------------------------------------------------------------------------
extern "C" void kernel_launch(void* const* d_in, const int* in_sizes, int n_in,
                              void* d_out, int out_size) {
    const float* invi  = (const float*)d_in[0];
    const float* eqi   = (const float*)d_in[1];
    const float* invh  = (const float*)d_in[2];
    const float* eqhid = (const float*)d_in[3];
    const float* Wl    = (const float*)d_in[4];
    const float* Wr    = (const float*)d_in[5];
    const float* Wii   = (const float*)d_in[6];
    const float* bii   = (const float*)d_in[7];
    const float* Wee   = (const float*)d_in[8];
    const float* Wdamp = (const float*)d_in[9];
    float* out = (float*)d_out;

    int Btot = in_sizes[0] / 64;

    prep_w_kernel<<<(FRAG_ELEMS + 255) / 256, 256>>>(Wii, Wdamp, Wl, Wr);

    int smem_bytes = (ROWS_PER_BLK * ASTR + ROWS_PER_BLK * 16 + 288) * 4;
    cudaFuncSetAttribute(rye_main, cudaFuncAttributeMaxDynamicSharedMemorySize, smem_bytes);
    rye_main<<<Btot / ROWS_PER_BLK, BDIM, smem_bytes>>>(invi, eqi, invh, eqhid,
                                                        bii, Wee, out, Btot);
}

// round 6
// speedup vs baseline: 2.2263x; 1.3432x over previous
#include <cuda_runtime.h>
#include <cuda_fp16.h>
#include <cstdint>
#include <cstddef>

// ---------------------------------------------------------------------------
// RyeElman, round 5: fp16 mma.sync m16n8k16 (sm_103-safe), fp32 accum.
//
//   proj[h] = sum_{c<=c'} Mn[c,c'] * G[(c,c'),h]   (Gram factorization)
//   One GEMM: A[B x 352] @ Wbig[352 x 144]
//     A = [inv_input(64) | inv_hidden(128) | Mn(153) | 0(7)]   (fp16)
//     Wbig = [[W_ii | W_damp]; [G | 0]]                         (fp16)
//   1024 threads/block, 128 rows/block, warps = 8(M) x 4(N), 5 n-tiles/warp
//   (n covered 0..159; tiles with n>=144 are zero-padded and discarded).
// ---------------------------------------------------------------------------

#define BDIM  1024
#define ROWSB 128
#define KD    192
#define NPAIR 153
#define NKS   22                 // 352 / 16
#define ASTR  368                // halves per A row (352 + pad)

// fragment-major B table: [t(22)][colW(4)][lane(32)][reg(12)] uint32 (half2)
#define TBL_REGS 12
#define TBL_ENTRIES (NKS * 4 * 32 * TBL_REGS)     // 33792
__device__ uint32_t d_WB[TBL_ENTRIES];

// smem float offsets
#define SF_BII  0
#define SF_WEE  128
#define SF_INVN 400                    // 128*17
#define SF_ES   2576                   // 128*52
#define SF_GS   9232                   // 128*16
#define SF_A    11280                  // A panel: 128*368 halves = 23552 floats
#define SF_TOTAL (SF_A + ROWSB * ASTR / 2)   // 34832 floats
#define ESTR 52

__device__ __forceinline__ void mma_f16(float* c, uint32_t a0, uint32_t a1,
                                        uint32_t a2, uint32_t a3,
                                        uint32_t b0, uint32_t b1) {
    asm volatile(
        "mma.sync.aligned.m16n8k16.row.col.f32.f16.f16.f32 "
        "{%0,%1,%2,%3}, {%4,%5,%6,%7}, {%8,%9}, {%0,%1,%2,%3};"
        : "+f"(c[0]), "+f"(c[1]), "+f"(c[2]), "+f"(c[3])
        : "r"(a0), "r"(a1), "r"(a2), "r"(a3), "r"(b0), "r"(b1));
}

// pair-permuted A column layout: within each 16-col group, pairs (k=2p,2p+1)
// stored at position ppos(p) = ((p&3)<<1)|(p>>2). Thread t4 then reads pairs
// t4 and t4+4 as ONE 8-byte LDS (positions 2*t4, 2*t4+1).
__device__ __forceinline__ int pair_off(int k) {          // k even
    int group = k >> 4, p = (k >> 1) & 7;
    int ppos = ((p & 3) << 1) | (p >> 2);
    return group * 16 + ppos * 2;
}
__device__ __forceinline__ int elem_off(int k) {          // any k
    return pair_off(k & ~1) + (k & 1);
}

__device__ __forceinline__ float fast_tanh(float x) {
    float ax = fabsf(x);
    float t  = __expf(-2.f * ax);
    float r  = (1.f - t) * __frcp_rn(1.f + t);
    return copysignf(r, x);
}

// ---------------------------------------------------------------------------
// K0: fragment-major fp16 weight table.
//   entry (t, colW, lane, reg): reg<10: tile=reg>>1, bsel=reg&1
//   n = colW*40 + tile*8 + (lane>>2),  k = t*16 + 2*(lane&3) + bsel*8
//   packs half2( Wbig(k,n), Wbig(k+1,n) );  n>=144 or reg>=10 -> 0.
// ---------------------------------------------------------------------------
__device__ __forceinline__ float wbig_val(int k, int n,
                                          const float* Wii, const float* Wdamp,
                                          const float* Wl,  const float* Wr) {
    if (n >= 144) return 0.f;
    if (k < KD) return (n < 128) ? Wii[k * 128 + n] : Wdamp[k * 16 + (n - 128)];
    if (k < KD + NPAIR && n < 128) {
        int p = k - KD, c = 0, rem = p;
        while (rem >= 17 - c) { rem -= 17 - c; c++; }
        int c2 = c + rem;
        float g = Wl[c * 128 + n] * Wr[c2 * 128 + n];
        if (c2 != c) g += Wl[c2 * 128 + n] * Wr[c * 128 + n];
        return g;
    }
    return 0.f;
}

__global__ void prep_w_kernel(const float* __restrict__ Wii,
                              const float* __restrict__ Wdamp,
                              const float* __restrict__ Wl,
                              const float* __restrict__ Wr) {
    int idx = blockIdx.x * blockDim.x + threadIdx.x;
    if (idx >= TBL_ENTRIES) return;
    int reg  = idx % TBL_REGS;
    int lane = (idx / TBL_REGS) % 32;
    int colW = (idx / (TBL_REGS * 32)) % 4;
    int t    = idx / (TBL_REGS * 32 * 4);
    float v0 = 0.f, v1 = 0.f;
    if (reg < 10) {
        int tile = reg >> 1, bsel = reg & 1;
        int n = colW * 40 + tile * 8 + (lane >> 2);
        int k = t * 16 + 2 * (lane & 3) + bsel * 8;
        v0 = wbig_val(k, n, Wii, Wdamp, Wl, Wr);
        v1 = wbig_val(k + 1, n, Wii, Wdamp, Wl, Wr);
    }
    __half2 h = __floats2half2_rn(v0, v1);
    d_WB[idx] = *reinterpret_cast<uint32_t*>(&h);
}

// ---------------------------------------------------------------------------
// K1: fused main kernel.
// ---------------------------------------------------------------------------
__global__ __launch_bounds__(BDIM, 1)
void rye_main(const float* __restrict__ invi, const float* __restrict__ eqi,
              const float* __restrict__ invh, const float* __restrict__ eqh,
              const float* __restrict__ bii,  const float* __restrict__ Wee,
              float* __restrict__ out, int Btot) {
    extern __shared__ float smf[];
    __half* As = reinterpret_cast<__half*>(smf + SF_A);
    float*  Es = smf + SF_ES;
    float*  invn_s = smf + SF_INVN;
    float*  Gs = smf + SF_GS;

    int tid = threadIdx.x, wid = tid >> 5, lane = tid & 31;
    size_t row0 = (size_t)blockIdx.x * ROWSB;

    // ---- Phase 1: stage everything ----
    for (int t = tid; t < ROWSB * 16; t += BDIM) {           // invi -> k [0,64)
        int r = t >> 4, q = t & 15, k0 = q * 4;
        float4 v = reinterpret_cast<const float4*>(invi + (row0 + r) * 64)[q];
        __half2 h0 = __floats2half2_rn(v.x, v.y), h1 = __floats2half2_rn(v.z, v.w);
        __half* Ar = As + r * ASTR;
        *reinterpret_cast<__half2*>(Ar + pair_off(k0))     = h0;
        *reinterpret_cast<__half2*>(Ar + pair_off(k0 + 2)) = h1;
    }
    for (int t = tid; t < ROWSB * 32; t += BDIM) {           // invh -> k [64,192)
        int r = t >> 5, q = t & 31, k0 = 64 + q * 4;
        float4 v = reinterpret_cast<const float4*>(invh + (row0 + r) * 128)[q];
        __half2 h0 = __floats2half2_rn(v.x, v.y), h1 = __floats2half2_rn(v.z, v.w);
        __half* Ar = As + r * ASTR;
        *reinterpret_cast<__half2*>(Ar + pair_off(k0))     = h0;
        *reinterpret_cast<__half2*>(Ar + pair_off(k0 + 2)) = h1;
    }
    for (int t = tid; t < ROWSB * 4; t += BDIM) {            // zero k [344,352)
        int r = t >> 2, j = t & 3;
        __half2 z; z.x = __ushort_as_half(0); z.y = __ushort_as_half(0);
        *reinterpret_cast<__half2*>(As + r * ASTR + pair_off(344 + j * 2)) = z;
    }
    for (int t = tid; t < ROWSB * 48; t += BDIM) {           // eqh -> Es
        int r = t / 48, q = t - r * 48;
        int s = q >> 4, c = q & 15;
        Es[r * ESTR + s * 17 + 1 + c] = eqh[(row0 + r) * 48 + q];
    }
    for (int t = tid; t < ROWSB * 3; t += BDIM) {            // eqi -> Es
        int r = t / 3, s = t - r * 3;
        Es[r * ESTR + s * 17] = eqi[(row0 + r) * 3 + s];
    }
    if (tid < 128) smf[SF_BII + tid] = bii[tid];
    if (tid < 272) smf[SF_WEE + tid] = Wee[tid];
    __syncthreads();

    // ---- Phase 2: 1/norm per (row, channel) ----
    for (int t = tid; t < ROWSB * 17; t += BDIM) {
        int r = t / 17, c = t - r * 17;
        float e0 = Es[r * ESTR + c], e1 = Es[r * ESTR + 17 + c], e2 = Es[r * ESTR + 34 + c];
        invn_s[t] = __frcp_rn(fmaf(e0, e0, fmaf(e1, e1, fmaf(e2, e2, 1e-6f))));
    }
    __syncthreads();

    // ---- Phase 3: Gram -> A k [192,345): 8 threads per row ----
    {
        int r = tid >> 3, sub = tid & 7;
        const float* E = Es + r * ESTR;
        const float* IN = invn_s + r * 17;
        __half* Ar = As + r * ASTR;
#pragma unroll
        for (int cs = 0; cs < 2; cs++) {
            int c = sub + cs * 8;                        // c in 0..15
            float e0 = E[c], e1 = E[17 + c], e2 = E[34 + c];
            float ic = IN[c];
            int pbase = c * 17 - (c * (c - 1)) / 2 - c;  // p = pbase + c2
            for (int c2 = c; c2 < 17; c2++) {
                float g = fmaf(e0, E[c2], fmaf(e1, E[17 + c2], e2 * E[34 + c2]));
                float m = g * ic * IN[c2];
                Ar[elem_off(KD + pbase + c2)] = __float2half(m);
            }
        }
        if (sub == 0) {                                  // c = 16 (p = 152)
            float g = fmaf(E[16], E[16], fmaf(E[33], E[33], E[50] * E[50]));
            float m = g * IN[16] * IN[16];
            Ar[elem_off(KD + 152)] = __float2half(m);
        }
    }
    __syncthreads();

    // ---- GEMM: 22 k-steps, B from global table (prefetch d=1), no barriers ----
    int mw = wid >> 2, colW = wid & 3;
    int m0 = mw * 16;
    int g = lane >> 2, t4 = lane & 3;

    float acc[5][4];
#pragma unroll
    for (int i = 0; i < 5; i++) acc[i][0] = acc[i][1] = acc[i][2] = acc[i][3] = 0.f;

    const __half* ArA = As + (m0 + g) * ASTR + t4 * 4;       // row g
    const __half* ArB = ArA + 8 * ASTR;                      // row g+8
    int ebase = (colW * 32 + lane) * TBL_REGS;               // + t*4*32*12

    uint4 f0; uint4 f1; uint2 f2;
    {
        const uint32_t* wp = d_WB + ebase;
        f0 = *reinterpret_cast<const uint4*>(wp);
        f1 = *reinterpret_cast<const uint4*>(wp + 4);
        f2 = *reinterpret_cast<const uint2*>(wp + 8);
    }
#pragma unroll 2
    for (int t = 0; t < NKS; t++) {
        uint32_t b[10] = { f0.x, f0.y, f0.z, f0.w, f1.x, f1.y, f1.z, f1.w, f2.x, f2.y };
        {
            int tn = (t < NKS - 1) ? t + 1 : t;
            const uint32_t* wp = d_WB + tn * (4 * 32 * TBL_REGS) + ebase;
            f0 = *reinterpret_cast<const uint4*>(wp);
            f1 = *reinterpret_cast<const uint4*>(wp + 4);
            f2 = *reinterpret_cast<const uint2*>(wp + 8);
        }
        uint2 aA = *reinterpret_cast<const uint2*>(ArA + t * 16);  // a0, a2
        uint2 aB = *reinterpret_cast<const uint2*>(ArB + t * 16);  // a1, a3
#pragma unroll
        for (int nt = 0; nt < 5; nt++)
            mma_f16(acc[nt], aA.x, aB.x, aA.y, aB.y, b[nt * 2], b[nt * 2 + 1]);
    }

    // ---- Epilogue: invariants (tanh+bias) -> out; gate cols -> Gs ----
    int lr = m0 + g;
#pragma unroll
    for (int nt = 0; nt < 5; nt++) {
        int j = colW * 40 + nt * 8 + 2 * t4;
        if (j < 128) {
            float b0 = smf[SF_BII + j], b1 = smf[SF_BII + j + 1];
            float2 v0 = make_float2(fast_tanh(acc[nt][0] + b0), fast_tanh(acc[nt][1] + b1));
            float2 v1 = make_float2(fast_tanh(acc[nt][2] + b0), fast_tanh(acc[nt][3] + b1));
            *reinterpret_cast<float2*>(&out[(row0 + lr) * 128 + j])     = v0;
            *reinterpret_cast<float2*>(&out[(row0 + lr + 8) * 128 + j]) = v1;
        } else if (j < 144) {
            int jc = j - 128;
            Gs[lr * 16 + jc]           = acc[nt][0];
            Gs[lr * 16 + jc + 1]       = acc[nt][1];
            Gs[(lr + 8) * 16 + jc]     = acc[nt][2];
            Gs[(lr + 8) * 16 + jc + 1] = acc[nt][3];
        }
    }
    __syncthreads();

    // ---- new_equivariant: one thread per (row, s) ----
    if (tid < ROWSB * 3) {
        int r = tid / 3, s = tid - r * 3;
        size_t row = row0 + r;
        const float* E = Es + r * ESTR + s * 17;
        const float* Wee_s = smf + SF_WEE;
        float4 res[4];
        float* rf = reinterpret_cast<float*>(res);
#pragma unroll
        for (int c = 0; c < 16; c++) {
            float sum = 0.f;
#pragma unroll
            for (int cc = 0; cc < 17; cc++) sum = fmaf(E[cc], Wee_s[cc * 16 + c], sum);
            rf[c] = fmaf(E[1 + c], Gs[r * 16 + c], sum);
        }
        float4* dst = reinterpret_cast<float4*>(out + (size_t)Btot * 128 + row * 48 + s * 16);
        dst[0] = res[0]; dst[1] = res[1]; dst[2] = res[2]; dst[3] = res[3];
    }
}

// ---------------------------------------------------------------------------
extern "C" void kernel_launch(void* const* d_in, const int* in_sizes, int n_in,
                              void* d_out, int out_size) {
    const float* invi  = (const float*)d_in[0];
    const float* eqi   = (const float*)d_in[1];
    const float* invh  = (const float*)d_in[2];
    const float* eqhid = (const float*)d_in[3];
    const float* Wl    = (const float*)d_in[4];
    const float* Wr    = (const float*)d_in[5];
    const float* Wii   = (const float*)d_in[6];
    const float* bii   = (const float*)d_in[7];
    const float* Wee   = (const float*)d_in[8];
    const float* Wdamp = (const float*)d_in[9];
    float* out = (float*)d_out;

    int Btot = in_sizes[0] / 64;

    prep_w_kernel<<<(TBL_ENTRIES + 255) / 256, 256>>>(Wii, Wdamp, Wl, Wr);

    int smem_bytes = SF_TOTAL * 4;
    cudaFuncSetAttribute(rye_main, cudaFuncAttributeMaxDynamicSharedMemorySize, smem_bytes);
    rye_main<<<Btot / ROWSB, BDIM, smem_bytes>>>(invi, eqi, invh, eqhid,
                                                 bii, Wee, out, Btot);
}